// round 11
// baseline (speedup 1.0000x reference)
#include <cuda_runtime.h>
#include <cuda_bf16.h>
#include <cstdint>

#define KAUG   136                   // 128 payload + 4 aug + 4 zeros (bf16)
#define PITCH  272                   // bytes/row: 17x16B, conflict-free (68 words = 4 banks)
#define TILE_B (128 * PITCH)         // 34816 B per 128-row tile

#define SM_X   0
#define SM_Y0  TILE_B
#define SM_Y1  (2 * TILE_B)
#define SMEM_TOTAL (3 * TILE_B)      // 104448 B -> 2 CTAs/SM

// augmented y copy, dense pitch KAUG (272B rows, tile slabs contiguous)
__device__ __nv_bfloat16 g_ya[32768 * KAUG];

__device__ __forceinline__ uint32_t smem_u32(const void* p) {
    uint32_t a;
    asm("{ .reg .u64 t; cvta.to.shared.u64 t, %1; cvt.u32.u64 %0, t; }" : "=r"(a) : "l"(p));
    return a;
}
__device__ __forceinline__ void cp_async16(uint32_t dst, const void* src) {
    asm volatile("cp.async.cg.shared.global [%0], [%1], 16;" :: "r"(dst), "l"(src));
}
__device__ __forceinline__ void cp_commit() {
    asm volatile("cp.async.commit_group;" ::: "memory");
}
template <int N>
__device__ __forceinline__ void cp_wait() {
    asm volatile("cp.async.wait_group %0;" :: "n"(N) : "memory");
}
__device__ __forceinline__ void bar_sync(int id, int count) {
    asm volatile("bar.sync %0, %1;" :: "r"(id), "r"(count) : "memory");
}
__device__ __forceinline__ void ldm_x4(uint32_t* r, uint32_t addr) {
    asm volatile("ldmatrix.sync.aligned.m8n8.x4.shared.b16 {%0,%1,%2,%3}, [%4];"
                 : "=r"(r[0]), "=r"(r[1]), "=r"(r[2]), "=r"(r[3]) : "r"(addr));
}
__device__ __forceinline__ void ldm_x2(uint32_t* r, uint32_t addr) {
    asm volatile("ldmatrix.sync.aligned.m8n8.x2.shared.b16 {%0,%1}, [%2];"
                 : "=r"(r[0]), "=r"(r[1]) : "r"(addr));
}
__device__ __forceinline__ void mma_bf16(float* c, const uint32_t* a, uint32_t b0, uint32_t b1) {
    asm volatile(
        "mma.sync.aligned.m16n8k16.row.col.f32.bf16.bf16.f32 "
        "{%0,%1,%2,%3},{%4,%5,%6,%7},{%8,%9},{%0,%1,%2,%3};"
        : "+f"(c[0]), "+f"(c[1]), "+f"(c[2]), "+f"(c[3])
        : "r"(a[0]), "r"(a[1]), "r"(a[2]), "r"(a[3]), "r"(b0), "r"(b1));
}
__device__ __forceinline__ void mma_bf16_k8(float* c, uint32_t a0, uint32_t a1, uint32_t b0) {
    asm volatile(
        "mma.sync.aligned.m16n8k8.row.col.f32.bf16.bf16.f32 "
        "{%0,%1,%2,%3},{%4,%5},{%6},{%0,%1,%2,%3};"
        : "+f"(c[0]), "+f"(c[1]), "+f"(c[2]), "+f"(c[3])
        : "r"(a0), "r"(a1), "r"(b0));
}

// One warp per y row: [y | 1 1 y2h y2l | 0 0 0 0]
__global__ void __launch_bounds__(256)
prep_kernel(const float* __restrict__ y) {
    int row = (blockIdx.x * 256 + threadIdx.x) >> 5;
    int lane = threadIdx.x & 31;
    const float* src = y + (size_t)row * 128;
    __nv_bfloat16* dst = g_ya + (size_t)row * KAUG;

    float4 v = *(const float4*)(src + lane * 4);
    float s = v.x * v.x + v.y * v.y + v.z * v.z + v.w * v.w;
#pragma unroll
    for (int o = 16; o; o >>= 1) s += __shfl_xor_sync(0xffffffffu, s, o);

    __nv_bfloat162 p0(__float2bfloat16(v.x), __float2bfloat16(v.y));
    __nv_bfloat162 p1(__float2bfloat16(v.z), __float2bfloat16(v.w));
    uint2 pk;
    pk.x = *(uint32_t*)&p0;
    pk.y = *(uint32_t*)&p1;
    *(uint2*)(dst + lane * 4) = pk;

    if (lane == 0) {
        __nv_bfloat16 h = __float2bfloat16(s);
        __nv_bfloat16 l = __float2bfloat16(s - __bfloat162float(h));
        __nv_bfloat16 one = __float2bfloat16(1.0f);
        __nv_bfloat162 hl(h, l), oo(one, one);
        uint4 tail;
        tail.x = *(uint32_t*)&oo; tail.y = *(uint32_t*)&hl;
        tail.z = 0u; tail.w = 0u;
        *(uint4*)(dst + 128) = tail;
    }
}

// y slab: per-warp — each warp loads the full 32 rows [n0w, n0w+32) it reads.
// Warps w and w+4 share a slab and both load it (duplicate identical writes: benign).
__device__ __forceinline__ void load_y_warp(uint32_t sdst, const __nv_bfloat16* __restrict__ g,
                                            int n0w, int lane) {
    const char* gb = (const char*)g;
    uint32_t base = (uint32_t)(n0w * PITCH);
#pragma unroll
    for (int i = 0; i < 17; ++i) {          // 32 rows * 17 chunks = 544 = 17*32
        uint32_t off = base + (uint32_t)(i * 32 + lane) * 16u;
        cp_async16(sdst + off, gb + off);
    }
}

__global__ void __launch_bounds__(256, 2)
pairwise_cost_kernel(const float* __restrict__ x, float* __restrict__ out) {
    extern __shared__ char smem[];
    const uint32_t sb = smem_u32(smem);
    const int tid = threadIdx.x, lane = tid & 31, wid = tid >> 5;

    const int bym = blockIdx.x;   // m tile (128 rows) — fastest: co-resident CTAs share y
    const int bxn = blockIdx.y;   // n-chunk (512 wide)
    const int bz  = blockIdx.z;   // batch

    const float* xg = x + (size_t)(bz * 2048 + bym * 128) * 128;
    const __nv_bfloat16* yg = g_ya + (size_t)(bz * 2048 + bxn * 512) * KAUG;

    // 8 warps: 2 m-groups x 4 n-groups, warp tile 64x32
    const int m0  = (wid >> 2) * 64;
    const int n0w = (wid & 3) * 32;
    const int pair_bar = 1 + (wid & 3);   // named barrier per slab pair {w, w+4}

    // y prefetches first (latency overlapped with x conversion below)
    load_y_warp(sb + SM_Y0, yg, n0w, lane);                 cp_commit();  // G1
    load_y_warp(sb + SM_Y1, yg + 128 * KAUG, n0w, lane);    cp_commit();  // G2

    // ---- inline x conversion: fp32 global -> augmented bf16 smem tile ----
    // row layout: [-2x | x2h x2l 1 1 | 0 0 0 0]  (one warp per row per iteration)
    {
        const __nv_bfloat16 one = __float2bfloat16(1.0f);
#pragma unroll
        for (int it = 0; it < 16; ++it) {
            int idx = it * 256 + tid;
            int r = idx >> 5, c4 = idx & 31;
            float4 v = *(const float4*)(xg + r * 128 + c4 * 4);
            float s = v.x * v.x + v.y * v.y + v.z * v.z + v.w * v.w;
#pragma unroll
            for (int o = 16; o; o >>= 1) s += __shfl_xor_sync(0xffffffffu, s, o);

            __nv_bfloat162 p0(__float2bfloat16(-2.f * v.x), __float2bfloat16(-2.f * v.y));
            __nv_bfloat162 p1(__float2bfloat16(-2.f * v.z), __float2bfloat16(-2.f * v.w));
            uint2 pk;
            pk.x = *(uint32_t*)&p0;
            pk.y = *(uint32_t*)&p1;
            *(uint2*)(smem + SM_X + r * PITCH + c4 * 8) = pk;

            if (lane == 0) {
                __nv_bfloat16 h = __float2bfloat16(s);
                __nv_bfloat16 l = __float2bfloat16(s - __bfloat162float(h));
                __nv_bfloat162 hl(h, l), oo(one, one);
                uint4 tail;
                tail.x = *(uint32_t*)&hl; tail.y = *(uint32_t*)&oo;
                tail.z = 0u; tail.w = 0u;
                *(uint4*)(smem + SM_X + r * PITCH + 256) = tail;
            }
        }
    }
    __syncthreads();              // x tile visible — only CTA-wide barrier

    // A ldmatrix: lanes 0-15 -> rows, lanes 16-31 -> +16B (k8-15)
    uint32_t baseA[4];
#pragma unroll
    for (int mf = 0; mf < 4; ++mf)
        baseA[mf] = sb + SM_X + (uint32_t)((m0 + 16 * mf + (lane & 15)) * PITCH)
                  + ((lane & 16) ? 16u : 0u);

    // B ldmatrix (k16): octets -> {n0-7,klo},{n0-7,khi},{n8-15,klo},{n8-15,khi}
    const uint32_t bnr = (uint32_t)(n0w + ((lane >> 4) & 1) * 8 + (lane & 7));
    const uint32_t bkb = ((lane >> 3) & 1) * 16u;
    uint32_t baseB[2];
    baseB[0] = bnr * PITCH + bkb;
    baseB[1] = (bnr + 16) * PITCH + bkb;

    // k8 tail: A rows at +256B; B 4 n8-octets at +256B (rows within [n0w, n0w+32))
    const uint32_t tailB = (uint32_t)((n0w + ((lane >> 3) & 3) * 8 + (lane & 7)) * PITCH) + 256u;

    float* og = out + (size_t)bz * 2048 * 2048;

#pragma unroll 1
    for (int t = 0; t < 4; ++t) {
        const uint32_t ybuf = (t & 1) ? SM_Y1 : SM_Y0;
        const uint32_t yb = sb + ybuf;

        // per-warp wait: this warp's own cp.async copies of y[t] are resident
        if (t < 3) cp_wait<1>(); else cp_wait<0>();

        float c[4][4][4] = {};

        // ---- 8 full k16 steps ----
#pragma unroll
        for (int kk = 0; kk < 8; ++kk) {
            uint32_t a[4][4], b[2][4];
#pragma unroll
            for (int mf = 0; mf < 4; ++mf) ldm_x4(a[mf], baseA[mf] + kk * 32u);
#pragma unroll
            for (int g = 0; g < 2; ++g)    ldm_x4(b[g], yb + baseB[g] + kk * 32u);
#pragma unroll
            for (int mf = 0; mf < 4; ++mf)
#pragma unroll
                for (int nf = 0; nf < 4; ++nf)
                    mma_bf16(c[mf][nf], a[mf],
                             b[nf >> 1][(nf & 1) * 2], b[nf >> 1][(nf & 1) * 2 + 1]);
        }

        // ---- k8 tail (aug columns 128..135) ----
        {
            uint32_t at[4][2], bt[4];
            ldm_x4(bt, yb + tailB);
#pragma unroll
            for (int mf = 0; mf < 4; ++mf)
                ldm_x2(at[mf], sb + SM_X +
                       (uint32_t)((m0 + 16 * mf + (lane & 15)) * PITCH) + 256u);
#pragma unroll
            for (int mf = 0; mf < 4; ++mf)
#pragma unroll
                for (int nf = 0; nf < 4; ++nf)
                    mma_bf16_k8(c[mf][nf], at[mf][0], at[mf][1], bt[nf]);
        }

        // pair-sync: partner warp (sharing this slab) must finish reading y[t]
        // before we overwrite the slab with y[t+2]; then prefetch.
        if (t < 2) {
            bar_sync(pair_bar, 64);
            load_y_warp(sb + ybuf, yg + (size_t)(t + 2) * 128 * KAUG, n0w, lane);
            cp_commit();
        }

        // ---- epilogue: D already equals cost; clamp and store ----
        const int ncol = bxn * 512 + t * 128 + n0w;
#pragma unroll
        for (int mf = 0; mf < 4; ++mf) {
#pragma unroll
            for (int e2 = 0; e2 < 2; ++e2) {
                int rowg = bym * 128 + m0 + 16 * mf + (lane >> 2) + 8 * e2;
                float* orow = og + (size_t)rowg * 2048 + ncol;
#pragma unroll
                for (int nf = 0; nf < 4; ++nf) {
                    float2 o;
                    o.x = fmaxf(c[mf][nf][e2 * 2 + 0], 0.f);
                    o.y = fmaxf(c[mf][nf][e2 * 2 + 1], 0.f);
                    *(float2*)&orow[8 * nf + 2 * (lane & 3)] = o;
                }
            }
        }
    }
}

extern "C" void kernel_launch(void* const* d_in, const int* in_sizes, int n_in,
                              void* d_out, int out_size) {
    const float* x = (const float*)d_in[0];
    const float* y = (const float*)d_in[1];
    float* out = (float*)d_out;
    prep_kernel<<<4096, 256>>>(y);
    cudaFuncSetAttribute(pairwise_cost_kernel,
                         cudaFuncAttributeMaxDynamicSharedMemorySize, SMEM_TOTAL);
    dim3 grid(16, 4, 16);   // bym fastest: co-resident CTAs share the same y chunk
    pairwise_cost_kernel<<<grid, 256, SMEM_TOTAL>>>(x, out);
}

// round 12
// speedup vs baseline: 1.0781x; 1.0781x over previous
#include <cuda_runtime.h>
#include <cuda_bf16.h>
#include <cstdint>

#define KAUG   136                   // 128 payload + 4 aug + 4 zeros (bf16)
#define PITCH  272                   // bytes/row: 17x16B, conflict-free (68 words = 4 banks)
#define TILE_B (128 * PITCH)         // 34816 B per 128-row tile
#define CHUNKS (128 * 17)            // 16B chunks per tile = 2176

#define SM_X   0
#define SM_Y0  TILE_B
#define SM_Y1  (2 * TILE_B)
#define SMEM_TOTAL (3 * TILE_B)      // 104448 B -> 2 CTAs/SM

// augmented bf16 copies, dense pitch KAUG (272B rows, tile slabs contiguous)
__device__ __nv_bfloat16 g_xa[32768 * KAUG];
__device__ __nv_bfloat16 g_ya[32768 * KAUG];

__device__ __forceinline__ uint32_t smem_u32(const void* p) {
    uint32_t a;
    asm("{ .reg .u64 t; cvta.to.shared.u64 t, %1; cvt.u32.u64 %0, t; }" : "=r"(a) : "l"(p));
    return a;
}
__device__ __forceinline__ void cp_async16(uint32_t dst, const void* src) {
    asm volatile("cp.async.cg.shared.global [%0], [%1], 16;" :: "r"(dst), "l"(src));
}
__device__ __forceinline__ void cp_commit() {
    asm volatile("cp.async.commit_group;" ::: "memory");
}
template <int N>
__device__ __forceinline__ void cp_wait() {
    asm volatile("cp.async.wait_group %0;" :: "n"(N) : "memory");
}
__device__ __forceinline__ void ldm_x4(uint32_t* r, uint32_t addr) {
    asm volatile("ldmatrix.sync.aligned.m8n8.x4.shared.b16 {%0,%1,%2,%3}, [%4];"
                 : "=r"(r[0]), "=r"(r[1]), "=r"(r[2]), "=r"(r[3]) : "r"(addr));
}
__device__ __forceinline__ void ldm_x2(uint32_t* r, uint32_t addr) {
    asm volatile("ldmatrix.sync.aligned.m8n8.x2.shared.b16 {%0,%1}, [%2];"
                 : "=r"(r[0]), "=r"(r[1]) : "r"(addr));
}
__device__ __forceinline__ void mma_bf16(float* c, const uint32_t* a, uint32_t b0, uint32_t b1) {
    asm volatile(
        "mma.sync.aligned.m16n8k16.row.col.f32.bf16.bf16.f32 "
        "{%0,%1,%2,%3},{%4,%5,%6,%7},{%8,%9},{%0,%1,%2,%3};"
        : "+f"(c[0]), "+f"(c[1]), "+f"(c[2]), "+f"(c[3])
        : "r"(a[0]), "r"(a[1]), "r"(a[2]), "r"(a[3]), "r"(b0), "r"(b1));
}
__device__ __forceinline__ void mma_bf16_k8(float* c, uint32_t a0, uint32_t a1, uint32_t b0) {
    asm volatile(
        "mma.sync.aligned.m16n8k8.row.col.f32.bf16.bf16.f32 "
        "{%0,%1,%2,%3},{%4,%5},{%6},{%0,%1,%2,%3};"
        : "+f"(c[0]), "+f"(c[1]), "+f"(c[2]), "+f"(c[3])
        : "r"(a0), "r"(a1), "r"(b0));
}

// One warp per input row: build augmented bf16 row.
// x rows: [-2x | x2h x2l 1 1 | 0 0 0 0]   y rows: [y | 1 1 y2h y2l | 0 0 0 0]
__global__ void __launch_bounds__(256)
prep_kernel(const float* __restrict__ x, const float* __restrict__ y) {
    int gw = (blockIdx.x * 256 + threadIdx.x) >> 5;
    int lane = threadIdx.x & 31;
    bool isx = gw < 32768;
    int row = isx ? gw : gw - 32768;
    const float* src = (isx ? x : y) + (size_t)row * 128;
    __nv_bfloat16* dst = (isx ? g_xa : g_ya) + (size_t)row * KAUG;

    float4 v = *(const float4*)(src + lane * 4);
    float s = v.x * v.x + v.y * v.y + v.z * v.z + v.w * v.w;
#pragma unroll
    for (int o = 16; o; o >>= 1) s += __shfl_xor_sync(0xffffffffu, s, o);

    float sc = isx ? -2.0f : 1.0f;
    __nv_bfloat162 p0(__float2bfloat16(v.x * sc), __float2bfloat16(v.y * sc));
    __nv_bfloat162 p1(__float2bfloat16(v.z * sc), __float2bfloat16(v.w * sc));
    uint2 pk;
    pk.x = *(uint32_t*)&p0;
    pk.y = *(uint32_t*)&p1;
    *(uint2*)(dst + lane * 4) = pk;

    if (lane == 0) {
        __nv_bfloat16 h = __float2bfloat16(s);
        __nv_bfloat16 l = __float2bfloat16(s - __bfloat162float(h));
        __nv_bfloat16 one = __float2bfloat16(1.0f);
        __nv_bfloat162 hl(h, l), oo(one, one);
        uint4 tail;
        if (isx) { tail.x = *(uint32_t*)&hl; tail.y = *(uint32_t*)&oo; }
        else     { tail.x = *(uint32_t*)&oo; tail.y = *(uint32_t*)&hl; }
        tail.z = 0u; tail.w = 0u;
        *(uint4*)(dst + 128) = tail;
    }
}

// x tile: cooperative (all 256 threads), identity slab copy
__device__ __forceinline__ void load_x_async(uint32_t sdst, const __nv_bfloat16* __restrict__ g,
                                             int tid) {
    const char* gb = (const char*)g;
#pragma unroll
    for (int i = 0; i < 9; ++i) {
        int idx = i * 256 + tid;
        if (idx < CHUNKS)
            cp_async16(sdst + (uint32_t)idx * 16u, gb + (size_t)idx * 16);
    }
}

// y slab: per-warp — each warp loads the full 32 rows [n0w, n0w+32) it reads.
// Warps w and w+4 share a slab and both load it (duplicate identical writes: benign).
__device__ __forceinline__ void load_y_warp(uint32_t sdst, const __nv_bfloat16* __restrict__ g,
                                            int n0w, int lane) {
    const char* gb = (const char*)g;
    uint32_t base = (uint32_t)(n0w * PITCH);
#pragma unroll
    for (int i = 0; i < 17; ++i) {          // 32 rows * 17 chunks = 544 = 17*32
        uint32_t off = base + (uint32_t)(i * 32 + lane) * 16u;
        cp_async16(sdst + off, gb + off);
    }
}

__global__ void __launch_bounds__(256, 2)
pairwise_cost_kernel(float* __restrict__ out) {
    extern __shared__ char smem[];
    const uint32_t sb = smem_u32(smem);
    const int tid = threadIdx.x, lane = tid & 31, wid = tid >> 5;

    const int bym = blockIdx.x;   // m tile (128 rows) — fastest: co-resident CTAs share y
    const int bxn = blockIdx.y;   // n-chunk (256 wide)
    const int bz  = blockIdx.z;   // batch

    const __nv_bfloat16* xg = g_xa + (size_t)(bz * 2048 + bym * 128) * KAUG;
    const __nv_bfloat16* yg = g_ya + (size_t)(bz * 2048 + bxn * 256) * KAUG;

    // 8 warps: 2 m-groups x 4 n-groups, warp tile 64x32
    const int m0  = (wid >> 2) * 64;
    const int n0w = (wid & 3) * 32;

    // both y slabs fit in smem: no in-loop prefetch, no slab overwrite, no pair bars
    load_x_async(sb + SM_X, xg, tid);                       cp_commit();  // G0
    load_y_warp(sb + SM_Y0, yg, n0w, lane);                 cp_commit();  // G1
    load_y_warp(sb + SM_Y1, yg + 128 * KAUG, n0w, lane);    cp_commit();  // G2

    // A ldmatrix: lanes 0-15 -> rows, lanes 16-31 -> +16B (k8-15)
    uint32_t baseA[4];
#pragma unroll
    for (int mf = 0; mf < 4; ++mf)
        baseA[mf] = sb + SM_X + (uint32_t)((m0 + 16 * mf + (lane & 15)) * PITCH)
                  + ((lane & 16) ? 16u : 0u);

    // B ldmatrix (k16): octets -> {n0-7,klo},{n0-7,khi},{n8-15,klo},{n8-15,khi}
    const uint32_t bnr = (uint32_t)(n0w + ((lane >> 4) & 1) * 8 + (lane & 7));
    const uint32_t bkb = ((lane >> 3) & 1) * 16u;
    uint32_t baseB[2];
    baseB[0] = bnr * PITCH + bkb;
    baseB[1] = (bnr + 16) * PITCH + bkb;

    // k8 tail: A rows at +256B; B 4 n8-octets at +256B (rows within [n0w, n0w+32))
    const uint32_t tailB = (uint32_t)((n0w + ((lane >> 3) & 3) * 8 + (lane & 7)) * PITCH) + 256u;

    cp_wait<2>();                 // G0 (x tile) complete
    __syncthreads();              // x visible to all warps — ONLY barrier in the kernel

    float* og = out + (size_t)bz * 2048 * 2048;

#pragma unroll 1
    for (int t = 0; t < 2; ++t) {
        const uint32_t yb = sb + ((t & 1) ? SM_Y1 : SM_Y0);

        // per-warp wait: this warp's own cp.async copies of y[t] are resident
        if (t == 0) cp_wait<1>(); else cp_wait<0>();

        float c[4][4][4] = {};

        // ---- 8 full k16 steps ----
#pragma unroll
        for (int kk = 0; kk < 8; ++kk) {
            uint32_t a[4][4], b[2][4];
#pragma unroll
            for (int mf = 0; mf < 4; ++mf) ldm_x4(a[mf], baseA[mf] + kk * 32u);
#pragma unroll
            for (int g = 0; g < 2; ++g)    ldm_x4(b[g], yb + baseB[g] + kk * 32u);
#pragma unroll
            for (int mf = 0; mf < 4; ++mf)
#pragma unroll
                for (int nf = 0; nf < 4; ++nf)
                    mma_bf16(c[mf][nf], a[mf],
                             b[nf >> 1][(nf & 1) * 2], b[nf >> 1][(nf & 1) * 2 + 1]);
        }

        // ---- k8 tail (aug columns 128..135) ----
        {
            uint32_t at[4][2], bt[4];
            ldm_x4(bt, yb + tailB);
#pragma unroll
            for (int mf = 0; mf < 4; ++mf)
                ldm_x2(at[mf], sb + SM_X +
                       (uint32_t)((m0 + 16 * mf + (lane & 15)) * PITCH) + 256u);
#pragma unroll
            for (int mf = 0; mf < 4; ++mf)
#pragma unroll
                for (int nf = 0; nf < 4; ++nf)
                    mma_bf16_k8(c[mf][nf], at[mf][0], at[mf][1], bt[nf]);
        }

        // ---- epilogue: D already equals cost; clamp and store ----
        const int ncol = bxn * 256 + t * 128 + n0w;
#pragma unroll
        for (int mf = 0; mf < 4; ++mf) {
#pragma unroll
            for (int e2 = 0; e2 < 2; ++e2) {
                int rowg = bym * 128 + m0 + 16 * mf + (lane >> 2) + 8 * e2;
                float* orow = og + (size_t)rowg * 2048 + ncol;
#pragma unroll
                for (int nf = 0; nf < 4; ++nf) {
                    float2 o;
                    o.x = fmaxf(c[mf][nf][e2 * 2 + 0], 0.f);
                    o.y = fmaxf(c[mf][nf][e2 * 2 + 1], 0.f);
                    *(float2*)&orow[8 * nf + 2 * (lane & 3)] = o;
                }
            }
        }
    }
}

extern "C" void kernel_launch(void* const* d_in, const int* in_sizes, int n_in,
                              void* d_out, int out_size) {
    const float* x = (const float*)d_in[0];
    const float* y = (const float*)d_in[1];
    float* out = (float*)d_out;
    prep_kernel<<<8192, 256>>>(x, y);
    cudaFuncSetAttribute(pairwise_cost_kernel,
                         cudaFuncAttributeMaxDynamicSharedMemorySize, SMEM_TOTAL);
    dim3 grid(16, 8, 16);   // bym fastest: co-resident CTAs share the same y chunk
    pairwise_cost_kernel<<<grid, 256, SMEM_TOTAL>>>(out);
}

// round 13
// speedup vs baseline: 1.1342x; 1.0521x over previous
#include <cuda_runtime.h>
#include <cuda_bf16.h>
#include <cstdint>

#define KAUG   136                   // 128 payload + 4 aug + 4 zeros (bf16)
#define PITCH  272                   // bytes/row: 17x16B, conflict-free (68 words = 4 banks)
#define TILE_B (128 * PITCH)         // 34816 B per 128-row tile
#define CHUNKS (128 * 17)            // 16B chunks per tile = 2176

#define SM_X   0
#define SM_Y0  TILE_B
#define SM_Y1  (2 * TILE_B)
#define SMEM_TOTAL (3 * TILE_B)      // 104448 B -> 2 CTAs/SM

// augmented bf16 copies, dense pitch KAUG (272B rows, tile slabs contiguous)
__device__ __nv_bfloat16 g_xa[32768 * KAUG];
__device__ __nv_bfloat16 g_ya[32768 * KAUG];

__device__ __forceinline__ uint32_t smem_u32(const void* p) {
    uint32_t a;
    asm("{ .reg .u64 t; cvta.to.shared.u64 t, %1; cvt.u32.u64 %0, t; }" : "=r"(a) : "l"(p));
    return a;
}
__device__ __forceinline__ void cp_async16(uint32_t dst, const void* src) {
    asm volatile("cp.async.cg.shared.global [%0], [%1], 16;" :: "r"(dst), "l"(src));
}
__device__ __forceinline__ void cp_commit() {
    asm volatile("cp.async.commit_group;" ::: "memory");
}
template <int N>
__device__ __forceinline__ void cp_wait() {
    asm volatile("cp.async.wait_group %0;" :: "n"(N) : "memory");
}
__device__ __forceinline__ void ldm_x4(uint32_t* r, uint32_t addr) {
    asm volatile("ldmatrix.sync.aligned.m8n8.x4.shared.b16 {%0,%1,%2,%3}, [%4];"
                 : "=r"(r[0]), "=r"(r[1]), "=r"(r[2]), "=r"(r[3]) : "r"(addr));
}
__device__ __forceinline__ void ldm_x2(uint32_t* r, uint32_t addr) {
    asm volatile("ldmatrix.sync.aligned.m8n8.x2.shared.b16 {%0,%1}, [%2];"
                 : "=r"(r[0]), "=r"(r[1]) : "r"(addr));
}
__device__ __forceinline__ void mma_bf16(float* c, const uint32_t* a, uint32_t b0, uint32_t b1) {
    asm volatile(
        "mma.sync.aligned.m16n8k16.row.col.f32.bf16.bf16.f32 "
        "{%0,%1,%2,%3},{%4,%5,%6,%7},{%8,%9},{%0,%1,%2,%3};"
        : "+f"(c[0]), "+f"(c[1]), "+f"(c[2]), "+f"(c[3])
        : "r"(a[0]), "r"(a[1]), "r"(a[2]), "r"(a[3]), "r"(b0), "r"(b1));
}
__device__ __forceinline__ void mma_bf16_k8(float* c, uint32_t a0, uint32_t a1, uint32_t b0) {
    asm volatile(
        "mma.sync.aligned.m16n8k8.row.col.f32.bf16.bf16.f32 "
        "{%0,%1,%2,%3},{%4,%5},{%6},{%0,%1,%2,%3};"
        : "+f"(c[0]), "+f"(c[1]), "+f"(c[2]), "+f"(c[3])
        : "r"(a0), "r"(a1), "r"(b0));
}
__device__ __forceinline__ void stcs2(float* p, float a, float b) {
    asm volatile("st.global.cs.v2.f32 [%0], {%1, %2};" :: "l"(p), "f"(a), "f"(b) : "memory");
}

// One warp per input row: build augmented bf16 row.
// x rows: [-2x | x2h x2l 1 1 | 0 0 0 0]   y rows: [y | 1 1 y2h y2l | 0 0 0 0]
__global__ void __launch_bounds__(256)
prep_kernel(const float* __restrict__ x, const float* __restrict__ y) {
    int gw = (blockIdx.x * 256 + threadIdx.x) >> 5;
    int lane = threadIdx.x & 31;
    bool isx = gw < 32768;
    int row = isx ? gw : gw - 32768;
    const float* src = (isx ? x : y) + (size_t)row * 128;
    __nv_bfloat16* dst = (isx ? g_xa : g_ya) + (size_t)row * KAUG;

    float4 v = *(const float4*)(src + lane * 4);
    float s = v.x * v.x + v.y * v.y + v.z * v.z + v.w * v.w;
#pragma unroll
    for (int o = 16; o; o >>= 1) s += __shfl_xor_sync(0xffffffffu, s, o);

    float sc = isx ? -2.0f : 1.0f;
    __nv_bfloat162 p0(__float2bfloat16(v.x * sc), __float2bfloat16(v.y * sc));
    __nv_bfloat162 p1(__float2bfloat16(v.z * sc), __float2bfloat16(v.w * sc));
    uint2 pk;
    pk.x = *(uint32_t*)&p0;
    pk.y = *(uint32_t*)&p1;
    *(uint2*)(dst + lane * 4) = pk;

    if (lane == 0) {
        __nv_bfloat16 h = __float2bfloat16(s);
        __nv_bfloat16 l = __float2bfloat16(s - __bfloat162float(h));
        __nv_bfloat16 one = __float2bfloat16(1.0f);
        __nv_bfloat162 hl(h, l), oo(one, one);
        uint4 tail;
        if (isx) { tail.x = *(uint32_t*)&hl; tail.y = *(uint32_t*)&oo; }
        else     { tail.x = *(uint32_t*)&oo; tail.y = *(uint32_t*)&hl; }
        tail.z = 0u; tail.w = 0u;
        *(uint4*)(dst + 128) = tail;
    }
}

// x tile: cooperative (all 256 threads), identity slab copy
__device__ __forceinline__ void load_x_async(uint32_t sdst, const __nv_bfloat16* __restrict__ g,
                                             int tid) {
    const char* gb = (const char*)g;
#pragma unroll
    for (int i = 0; i < 9; ++i) {
        int idx = i * 256 + tid;
        if (idx < CHUNKS)
            cp_async16(sdst + (uint32_t)idx * 16u, gb + (size_t)idx * 16);
    }
}

// y slab: one warp loads 32 rows [n0w, n0w+32) of one tile — NO duplication.
__device__ __forceinline__ void load_y_warp(uint32_t sdst, const __nv_bfloat16* __restrict__ g,
                                            int n0w, int lane) {
    const char* gb = (const char*)g;
    uint32_t base = (uint32_t)(n0w * PITCH);
#pragma unroll
    for (int i = 0; i < 17; ++i) {          // 32 rows * 17 chunks = 544 = 17*32
        uint32_t off = base + (uint32_t)(i * 32 + lane) * 16u;
        cp_async16(sdst + off, gb + off);
    }
}

__global__ void __launch_bounds__(256, 2)
pairwise_cost_kernel(float* __restrict__ out) {
    extern __shared__ char smem[];
    const uint32_t sb = smem_u32(smem);
    const int tid = threadIdx.x, lane = tid & 31, wid = tid >> 5;

    const int bym = blockIdx.x;   // m tile (128 rows) — fastest: co-resident CTAs share y
    const int bxn = blockIdx.y;   // n-chunk (256 wide)
    const int bz  = blockIdx.z;   // batch

    const __nv_bfloat16* xg = g_xa + (size_t)(bz * 2048 + bym * 128) * KAUG;
    const __nv_bfloat16* yg = g_ya + (size_t)(bz * 2048 + bxn * 256) * KAUG;

    // 8 warps: 2 m-groups x 4 n-groups, warp tile 64x32
    const int m0  = (wid >> 2) * 64;
    const int n0w = (wid & 3) * 32;

    // upfront loads, deduplicated:
    //   all warps: their tid-stride share of the x tile
    //   warps 0-3: slab (wid&3) of Y0;  warps 4-7: slab (wid&3) of Y1
    load_x_async(sb + SM_X, xg, tid);
    {
        const uint32_t ydst = (wid < 4) ? (sb + SM_Y0) : (sb + SM_Y1);
        const __nv_bfloat16* ysrc = (wid < 4) ? yg : (yg + 128 * KAUG);
        load_y_warp(ydst, ysrc, n0w, lane);
    }
    cp_commit();

    // A ldmatrix: lanes 0-15 -> rows, lanes 16-31 -> +16B (k8-15)
    uint32_t baseA[4];
#pragma unroll
    for (int mf = 0; mf < 4; ++mf)
        baseA[mf] = sb + SM_X + (uint32_t)((m0 + 16 * mf + (lane & 15)) * PITCH)
                  + ((lane & 16) ? 16u : 0u);

    // B ldmatrix (k16): octets -> {n0-7,klo},{n0-7,khi},{n8-15,klo},{n8-15,khi}
    const uint32_t bnr = (uint32_t)(n0w + ((lane >> 4) & 1) * 8 + (lane & 7));
    const uint32_t bkb = ((lane >> 3) & 1) * 16u;
    uint32_t baseB[2];
    baseB[0] = bnr * PITCH + bkb;
    baseB[1] = (bnr + 16) * PITCH + bkb;

    // k8 tail: A rows at +256B; B 4 n8-octets at +256B (rows within [n0w, n0w+32))
    const uint32_t tailB = (uint32_t)((n0w + ((lane >> 3) & 3) * 8 + (lane & 7)) * PITCH) + 256u;

    cp_wait<0>();                 // all of this warp's copies complete
    __syncthreads();              // everything visible CTA-wide — only barrier

    float* og = out + (size_t)bz * 2048 * 2048;

#pragma unroll 1
    for (int t = 0; t < 2; ++t) {
        const uint32_t yb = sb + ((t & 1) ? SM_Y1 : SM_Y0);

        float c[4][4][4] = {};

        // ---- 8 full k16 steps ----
#pragma unroll
        for (int kk = 0; kk < 8; ++kk) {
            uint32_t a[4][4], b[2][4];
#pragma unroll
            for (int mf = 0; mf < 4; ++mf) ldm_x4(a[mf], baseA[mf] + kk * 32u);
#pragma unroll
            for (int g = 0; g < 2; ++g)    ldm_x4(b[g], yb + baseB[g] + kk * 32u);
#pragma unroll
            for (int mf = 0; mf < 4; ++mf)
#pragma unroll
                for (int nf = 0; nf < 4; ++nf)
                    mma_bf16(c[mf][nf], a[mf],
                             b[nf >> 1][(nf & 1) * 2], b[nf >> 1][(nf & 1) * 2 + 1]);
        }

        // ---- k8 tail (aug columns 128..135) ----
        {
            uint32_t at[4][2], bt[4];
            ldm_x4(bt, yb + tailB);
#pragma unroll
            for (int mf = 0; mf < 4; ++mf)
                ldm_x2(at[mf], sb + SM_X +
                       (uint32_t)((m0 + 16 * mf + (lane & 15)) * PITCH) + 256u);
#pragma unroll
            for (int mf = 0; mf < 4; ++mf)
#pragma unroll
                for (int nf = 0; nf < 4; ++nf)
                    mma_bf16_k8(c[mf][nf], at[mf][0], at[mf][1], bt[nf]);
        }

        // ---- epilogue: D already equals cost; clamp + streaming (evict-first) stores ----
        const int ncol = bxn * 256 + t * 128 + n0w;
#pragma unroll
        for (int mf = 0; mf < 4; ++mf) {
#pragma unroll
            for (int e2 = 0; e2 < 2; ++e2) {
                int rowg = bym * 128 + m0 + 16 * mf + (lane >> 2) + 8 * e2;
                float* orow = og + (size_t)rowg * 2048 + ncol;
#pragma unroll
                for (int nf = 0; nf < 4; ++nf) {
                    stcs2(&orow[8 * nf + 2 * (lane & 3)],
                          fmaxf(c[mf][nf][e2 * 2 + 0], 0.f),
                          fmaxf(c[mf][nf][e2 * 2 + 1], 0.f));
                }
            }
        }
    }
}

extern "C" void kernel_launch(void* const* d_in, const int* in_sizes, int n_in,
                              void* d_out, int out_size) {
    const float* x = (const float*)d_in[0];
    const float* y = (const float*)d_in[1];
    float* out = (float*)d_out;
    prep_kernel<<<8192, 256>>>(x, y);
    cudaFuncSetAttribute(pairwise_cost_kernel,
                         cudaFuncAttributeMaxDynamicSharedMemorySize, SMEM_TOTAL);
    dim3 grid(16, 8, 16);   // bym fastest: co-resident CTAs share the same y chunk
    pairwise_cost_kernel<<<grid, 256, SMEM_TOTAL>>>(out);
}